// round 12
// baseline (speedup 1.0000x reference)
#include <cuda_runtime.h>
#include <cuda_fp16.h>
#include <cstdint>

#define NN 100000
#define NE 1600000
#define IN_CH 128
#define OUT_CH 64
#define NKSTEPS (IN_CH / 16)   // 8

// Scratch (device globals: no allocation allowed in kernel_launch).
__device__ int     g_deg[NN];
__device__ float   g_dinv[NN];
__device__ __half2 g_half[(size_t)NN * 32];   // g = (x@W)*dinv[row], fp16, 12.8 MB
__device__ unsigned long long g_scan_state[512];   // decoupled-lookback flags
__device__ int     g_row_start[NN + 1];
__device__ int     g_cursor[NN];
__device__ int     g_csr_src[NE];

// ---------------------------------------------------------------------------
// 1) degree counting (in-degree by target col). int32 indices.
//    (g_deg / g_scan_state zeroed by cudaMemsetAsync host-side.)
// ---------------------------------------------------------------------------
__global__ void count_deg_kernel(const int* __restrict__ ei, int n_edges) {
    int e = blockIdx.x * blockDim.x + threadIdx.x;
    if (e < n_edges) {
        int row = ei[e];
        int col = ei[n_edges + e];
        if ((unsigned)row < NN && (unsigned)col < NN)   // must match fill guard
            atomicAdd(&g_deg[col], 1);
    }
}

// ---------------------------------------------------------------------------
// 1b) single-pass exclusive scan (decoupled lookback).
//     All 391 blocks are co-resident on 148 SMs -> spin is deadlock-free.
//     Writes row_start, cursor, and fused dinv.
// ---------------------------------------------------------------------------
__global__ void scan_kernel(int n) {
    __shared__ int s[256];
    __shared__ int s_prefix;
    const int bid = blockIdx.x;
    const int i   = bid * 256 + threadIdx.x;
    const int v   = (i < n) ? g_deg[i] : 0;

    // intra-block inclusive scan
    s[threadIdx.x] = v;
    __syncthreads();
    for (int off = 1; off < 256; off <<= 1) {
        int u = (threadIdx.x >= off) ? s[threadIdx.x - off] : 0;
        __syncthreads();
        s[threadIdx.x] += u;
        __syncthreads();
    }
    const int incl = s[threadIdx.x];
    const int agg  = s[255];

    if (threadIdx.x == 0) {
        if (bid == 0) {
            atomicExch(&g_scan_state[0], (2ULL << 62) | (unsigned)agg);
            s_prefix = 0;
        } else {
            atomicExch(&g_scan_state[bid], (1ULL << 62) | (unsigned)agg);
            int pre = 0;
            int t = bid - 1;
            while (true) {
                unsigned long long st = atomicAdd(&g_scan_state[t], 0ULL);
                unsigned long long flag = st >> 62;
                if (flag == 0) { __nanosleep(20); continue; }
                pre += (int)(st & 0xffffffffULL);
                if (flag == 2ULL) break;   // inclusive prefix found
                t--;                       // aggregate only: keep walking
            }
            atomicExch(&g_scan_state[bid], (2ULL << 62) | (unsigned)(pre + agg));
            s_prefix = pre;
        }
    }
    __syncthreads();

    const int excl = s_prefix + incl - v;
    if (i < n) {
        g_row_start[i] = excl;
        g_cursor[i]    = excl;
        g_dinv[i]      = rsqrtf((float)(v + 1));   // +1 self loop (fused)
        if (i == n - 1) g_row_start[n] = excl + v;
    }
}

// ---------------------------------------------------------------------------
// 1c) fill CSR: for each edge, place src at cursor[col]++
// ---------------------------------------------------------------------------
__global__ void fill_csr_kernel(const int* __restrict__ ei, int n_edges) {
    int e = blockIdx.x * blockDim.x + threadIdx.x;
    if (e < n_edges) {
        int row = ei[e];
        int col = ei[n_edges + e];
        if ((unsigned)row < NN && (unsigned)col < NN) {
            int pos = atomicAdd(&g_cursor[col], 1);
            g_csr_src[pos] = row;
        }
    }
}

// ---------------------------------------------------------------------------
// 2) h = x @ W via tf32 mma.sync, 3-stage cp.async pipeline.
//    g = h * dinv[row] -> g_half (fp16).
// ---------------------------------------------------------------------------
__device__ __forceinline__ unsigned f2tf32(float f) {
    unsigned r;
    asm("cvt.rna.tf32.f32 %0, %1;" : "=r"(r) : "f"(f));
    return r;
}

__device__ __forceinline__ void mma_tf32(float c[4], const unsigned a[4],
                                         const unsigned b[2]) {
    asm volatile(
        "mma.sync.aligned.m16n8k8.row.col.f32.tf32.tf32.f32 "
        "{%0,%1,%2,%3}, {%4,%5,%6,%7}, {%8,%9}, {%0,%1,%2,%3};"
        : "+f"(c[0]), "+f"(c[1]), "+f"(c[2]), "+f"(c[3])
        : "r"(a[0]), "r"(a[1]), "r"(a[2]), "r"(a[3]), "r"(b[0]), "r"(b[1]));
}

__device__ __forceinline__ void cp16(void* smem_dst, const void* gmem_src, bool pred) {
    unsigned saddr = (unsigned)__cvta_generic_to_shared(smem_dst);
    int sz = pred ? 16 : 0;
    asm volatile("cp.async.cg.shared.global [%0], [%1], 16, %2;"
                 :: "r"(saddr), "l"(gmem_src), "r"(sz));
}
#define CP_COMMIT()  asm volatile("cp.async.commit_group;")
#define CP_WAIT(N)   asm volatile("cp.async.wait_group %0;" :: "n"(N))

#define AS_STRIDE 20
#define BS_STRIDE 68

__global__ __launch_bounds__(256) void gemm_tc_kernel(
    const float* __restrict__ x, const float* __restrict__ W, int n)
{
    __shared__ unsigned As[3][128 * AS_STRIDE];  // raw f32 bits
    __shared__ unsigned Bs[3][16 * BS_STRIDE];

    const int tid  = threadIdx.x;
    const int wid  = tid >> 5;
    const int lane = tid & 31;
    const int gid  = lane >> 2;
    const int tig  = lane & 3;
    const int wm   = wid & 3;
    const int wn   = wid >> 2;
    const int m0   = blockIdx.x * 128;

    const int r0  = tid >> 2;
    const int r1  = r0 + 64;
    const int c4x = (tid & 3) * 4;
    const int rW  = tid >> 4;
    const int c4W = (tid & 15) * 4;

    auto load_stage = [&](int st, int bk) {
        const int k0 = bk * 16;
        {
            const int gr = m0 + r0;
            const bool p = gr < n;
            const float* src = x + (size_t)(p ? gr : 0) * IN_CH + k0 + c4x;
            cp16(&As[st][r0 * AS_STRIDE + c4x], src, p);
        }
        {
            const int gr = m0 + r1;
            const bool p = gr < n;
            const float* src = x + (size_t)(p ? gr : 0) * IN_CH + k0 + c4x;
            cp16(&As[st][r1 * AS_STRIDE + c4x], src, p);
        }
        cp16(&Bs[st][rW * BS_STRIDE + c4W], W + (size_t)(k0 + rW) * OUT_CH + c4W, true);
        CP_COMMIT();
    };

    float c[2][4][4];
#pragma unroll
    for (int s = 0; s < 2; s++)
#pragma unroll
        for (int t = 0; t < 4; t++)
#pragma unroll
            for (int f = 0; f < 4; f++) c[s][t][f] = 0.0f;

    load_stage(0, 0);
    load_stage(1, 1);

    for (int bk = 0; bk < NKSTEPS; bk++) {
        const int cur = bk % 3;
        if (bk + 2 < NKSTEPS) {
            load_stage((bk + 2) % 3, bk + 2);
            CP_WAIT(2);
        } else if (bk + 1 < NKSTEPS) {
            CP_WAIT(1);
        } else {
            CP_WAIT(0);
        }
        __syncthreads();

#pragma unroll
        for (int ks = 0; ks < 2; ks++) {
            const int kb = ks * 8;
            unsigned a[2][4];
#pragma unroll
            for (int s = 0; s < 2; s++) {
                const int rbase = (wm * 32 + s * 16 + gid) * AS_STRIDE;
                a[s][0] = f2tf32(__uint_as_float(As[cur][rbase + kb + tig]));
                a[s][1] = f2tf32(__uint_as_float(As[cur][rbase + 8 * AS_STRIDE + kb + tig]));
                a[s][2] = f2tf32(__uint_as_float(As[cur][rbase + kb + tig + 4]));
                a[s][3] = f2tf32(__uint_as_float(As[cur][rbase + 8 * AS_STRIDE + kb + tig + 4]));
            }
            unsigned b[4][2];
#pragma unroll
            for (int t = 0; t < 4; t++) {
                const int nb = wn * 32 + t * 8 + gid;
                b[t][0] = f2tf32(__uint_as_float(Bs[cur][(kb + tig) * BS_STRIDE + nb]));
                b[t][1] = f2tf32(__uint_as_float(Bs[cur][(kb + tig + 4) * BS_STRIDE + nb]));
            }
#pragma unroll
            for (int s = 0; s < 2; s++)
#pragma unroll
                for (int t = 0; t < 4; t++)
                    mma_tf32(c[s][t], a[s], b[t]);
        }
        __syncthreads();
    }

    // epilogue: scale by dinv[row], convert to fp16, write g_half
#pragma unroll
    for (int s = 0; s < 2; s++) {
#pragma unroll
        for (int h = 0; h < 2; h++) {
            const int row = m0 + wm * 32 + s * 16 + gid + h * 8;
            if (row < n) {
                const float di = g_dinv[row];
#pragma unroll
                for (int t = 0; t < 4; t++) {
                    const int col = wn * 32 + t * 8 + tig * 2;
                    const float vx = c[s][t][h * 2 + 0] * di;
                    const float vy = c[s][t][h * 2 + 1] * di;
                    g_half[(size_t)row * 32 + (col >> 1)] = __floats2half2_rn(vx, vy);
                }
            }
        }
    }
}

// ---------------------------------------------------------------------------
// 3) pull v3: one warp per node, QUARTER-WARP (8 lanes) per source row.
//    Each lane loads uint4 (16 B = 8 cols); 16 distinct rows in flight per
//    16-edge batch (4 LDG.128 warp-instructions). Two-level shfl_xor combine.
// ---------------------------------------------------------------------------
__device__ __forceinline__ float2 h2f2(unsigned u) {
    return __half22float2(*(__half2*)&u);
}

__global__ __launch_bounds__(256) void pull_kernel(
    float* __restrict__ out, const float* __restrict__ bias, int n)
{
    const int warp = (blockIdx.x * 256 + threadIdx.x) >> 5;
    const int lane = threadIdx.x & 31;
    if (warp >= n) return;
    const int q  = lane >> 3;        // quarter 0..3
    const int ql = lane & 7;         // lane in quarter

    const int start = g_row_start[warp];
    const int end   = g_row_start[warp + 1];

    const uint4* rows = (const uint4*)g_half;   // 8 uint4 (128 B) per row

    float2 a0 = make_float2(0.f, 0.f), a1 = a0, a2 = a0, a3 = a0;

    // self loop g[c] — quarter 0 only (counted once after combine)
    if (q == 0) {
        uint4 r = rows[(size_t)warp * 8 + ql];
        a0 = h2f2(r.x); a1 = h2f2(r.y); a2 = h2f2(r.z); a3 = h2f2(r.w);
    }

    for (int j = start; j < end; j += 32) {
        const int id  = (j + lane < end) ? g_csr_src[j + lane] : 0;
        const int cnt = min(32, end - j);
        for (int k = 0; k < cnt; k += 16) {
            uint4 raw[4];
#pragma unroll
            for (int u = 0; u < 4; u++) {
                const int idx = k + u * 4 + q;           // this quarter's edge
                const int src = __shfl_sync(0xffffffff, id, idx & 31);
                raw[u] = (idx < cnt) ? rows[(size_t)src * 8 + ql]
                                     : make_uint4(0u, 0u, 0u, 0u);
            }
#pragma unroll
            for (int u = 0; u < 4; u++) {
                float2 t;
                t = h2f2(raw[u].x); a0.x += t.x; a0.y += t.y;
                t = h2f2(raw[u].y); a1.x += t.x; a1.y += t.y;
                t = h2f2(raw[u].z); a2.x += t.x; a2.y += t.y;
                t = h2f2(raw[u].w); a3.x += t.x; a3.y += t.y;
            }
        }
    }

    // combine quarters: xor 8 then xor 16
#pragma unroll
    for (int d = 8; d <= 16; d <<= 1) {
        a0.x += __shfl_xor_sync(0xffffffff, a0.x, d);
        a0.y += __shfl_xor_sync(0xffffffff, a0.y, d);
        a1.x += __shfl_xor_sync(0xffffffff, a1.x, d);
        a1.y += __shfl_xor_sync(0xffffffff, a1.y, d);
        a2.x += __shfl_xor_sync(0xffffffff, a2.x, d);
        a2.y += __shfl_xor_sync(0xffffffff, a2.y, d);
        a3.x += __shfl_xor_sync(0xffffffff, a3.x, d);
        a3.y += __shfl_xor_sync(0xffffffff, a3.y, d);
    }

    if (lane < 8) {                  // q == 0 writes cols [ql*8, ql*8+8)
        const float di = g_dinv[warp];
        const float4 b0 = ((const float4*)bias)[ql * 2 + 0];
        const float4 b1 = ((const float4*)bias)[ql * 2 + 1];
        float4 o0, o1;
        o0.x = a0.x * di + b0.x;  o0.y = a0.y * di + b0.y;
        o0.z = a1.x * di + b0.z;  o0.w = a1.y * di + b0.w;
        o1.x = a2.x * di + b1.x;  o1.y = a2.y * di + b1.y;
        o1.z = a3.x * di + b1.z;  o1.w = a3.y * di + b1.w;
        ((float4*)out)[(size_t)warp * 16 + ql * 2 + 0] = o0;
        ((float4*)out)[(size_t)warp * 16 + ql * 2 + 1] = o1;
    }
}

// ---------------------------------------------------------------------------
extern "C" void kernel_launch(void* const* d_in, const int* in_sizes, int n_in,
                              void* d_out, int out_size)
{
    const float* x  = (const float*)d_in[0];
    const int*   ei = (const int*)d_in[1];     // int32 edge_index [2, E]
    const float* W  = (const float*)d_in[2];
    const float* b  = (const float*)d_in[3];
    float*       out = (float*)d_out;

    const int n = in_sizes[0] / IN_CH;   // 100000
    const int e = in_sizes[1] / 2;       // 1600000

    void* p = nullptr;
    cudaGetSymbolAddress(&p, g_deg);
    cudaMemsetAsync(p, 0, (size_t)n * sizeof(int));
    cudaGetSymbolAddress(&p, g_scan_state);
    cudaMemsetAsync(p, 0, 512 * sizeof(unsigned long long));

    count_deg_kernel<<<(e + 255) / 256, 256>>>(ei, e);

    const int nb = (n + 255) / 256;
    scan_kernel<<<nb, 256>>>(n);     // single-pass lookback scan + dinv

    gemm_tc_kernel<<<(n + 127) / 128, 256>>>(x, W, n);

    fill_csr_kernel<<<(e + 255) / 256, 256>>>(ei, e);

    pull_kernel<<<(n * 32 + 255) / 256, 256>>>(out, b, n);
}

// round 13
// speedup vs baseline: 1.0692x; 1.0692x over previous
#include <cuda_runtime.h>
#include <cuda_fp16.h>
#include <cstdint>

#define NN 100000
#define NE 1600000
#define IN_CH 128
#define OUT_CH 64
#define NKSTEPS (IN_CH / 16)   // 8

// Scratch (device globals: no allocation allowed in kernel_launch).
__device__ int     g_deg[NN];
__device__ float   g_dinv[NN];
__device__ __half2 g_half[(size_t)NN * 32];   // g = (x@W)*dinv[row], fp16, 12.8 MB
__device__ unsigned long long g_scan_state[512];   // decoupled-lookback flags
__device__ int     g_row_start[NN + 1];
__device__ int     g_cursor[NN];
__device__ int     g_csr_src[NE];

// ---------------------------------------------------------------------------
// 1) degree counting (in-degree by target col), x4 unrolled. int32 indices.
//    (g_deg / g_scan_state zeroed by cudaMemsetAsync host-side.)
// ---------------------------------------------------------------------------
__global__ void count_deg_kernel(const int* __restrict__ ei, int n_edges) {
    const int e4 = (blockIdx.x * blockDim.x + threadIdx.x) * 4;
    if (e4 + 3 < n_edges) {
        const int4 r = *(const int4*)(ei + e4);
        const int4 c = *(const int4*)(ei + n_edges + e4);
        if ((unsigned)r.x < NN && (unsigned)c.x < NN) atomicAdd(&g_deg[c.x], 1);
        if ((unsigned)r.y < NN && (unsigned)c.y < NN) atomicAdd(&g_deg[c.y], 1);
        if ((unsigned)r.z < NN && (unsigned)c.z < NN) atomicAdd(&g_deg[c.z], 1);
        if ((unsigned)r.w < NN && (unsigned)c.w < NN) atomicAdd(&g_deg[c.w], 1);
    } else {
        for (int e = e4; e < n_edges; e++) {
            const int row = ei[e];
            const int col = ei[n_edges + e];
            if ((unsigned)row < NN && (unsigned)col < NN)
                atomicAdd(&g_deg[col], 1);
        }
    }
}

// ---------------------------------------------------------------------------
// 1b) single-pass exclusive scan, WARP-PARALLEL decoupled lookback.
//     Warp 0 scans 32 predecessor states per step (ballot + warp reduce);
//     worst case ~13 steps instead of ~390 serial L2 reads.
//     Writes row_start, cursor, and fused dinv.
// ---------------------------------------------------------------------------
__global__ void scan_kernel(int n) {
    __shared__ int s[256];
    __shared__ int s_prefix;
    const int bid = blockIdx.x;
    const int i   = bid * 256 + threadIdx.x;
    const int v   = (i < n) ? g_deg[i] : 0;

    // intra-block inclusive scan
    s[threadIdx.x] = v;
    __syncthreads();
    for (int off = 1; off < 256; off <<= 1) {
        int u = (threadIdx.x >= off) ? s[threadIdx.x - off] : 0;
        __syncthreads();
        s[threadIdx.x] += u;
        __syncthreads();
    }
    const int incl = s[threadIdx.x];
    const int agg  = s[255];

    if (threadIdx.x < 32) {
        const int lane = threadIdx.x;
        if (bid == 0) {
            if (lane == 0) {
                atomicExch(&g_scan_state[0], (2ULL << 62) | (unsigned)agg);
                s_prefix = 0;
            }
        } else {
            if (lane == 0)
                atomicExch(&g_scan_state[bid], (1ULL << 62) | (unsigned)agg);
            __syncwarp();

            int pre  = 0;
            int wend = bid;                    // exclusive window end
            while (true) {
                const int idx = wend - 32 + lane;
                unsigned long long st = (idx >= 0)
                    ? atomicAdd(&g_scan_state[idx], 0ULL)
                    : (2ULL << 62);            // virtual prefix 0 before block 0
                while ((st >> 62) == 0ULL) {   // not yet published
                    __nanosleep(20);
                    st = atomicAdd(&g_scan_state[idx], 0ULL);
                }
                const unsigned done = __ballot_sync(0xffffffff, (st >> 62) == 2ULL);
                int val = (idx >= 0) ? (int)(st & 0xffffffffULL) : 0;
                if (done) {
                    const int highest = 31 - __clz(done);   // nearest inclusive prefix
                    if (lane < highest) val = 0;            // covered by the prefix
#pragma unroll
                    for (int d = 16; d; d >>= 1) val += __shfl_down_sync(0xffffffff, val, d);
                    pre += __shfl_sync(0xffffffff, val, 0);
                    break;
                } else {                                    // all aggregates: take window, continue
#pragma unroll
                    for (int d = 16; d; d >>= 1) val += __shfl_down_sync(0xffffffff, val, d);
                    pre += __shfl_sync(0xffffffff, val, 0);
                    wend -= 32;
                }
            }
            if (lane == 0) {
                atomicExch(&g_scan_state[bid], (2ULL << 62) | (unsigned)(pre + agg));
                s_prefix = pre;
            }
        }
    }
    __syncthreads();

    const int excl = s_prefix + incl - v;
    if (i < n) {
        g_row_start[i] = excl;
        g_cursor[i]    = excl;
        g_dinv[i]      = rsqrtf((float)(v + 1));   // +1 self loop (fused)
        if (i == n - 1) g_row_start[n] = excl + v;
    }
}

// ---------------------------------------------------------------------------
// 1c) fill CSR, x4 unrolled: 4 independent atomic->store chains per thread.
// ---------------------------------------------------------------------------
__global__ void fill_csr_kernel(const int* __restrict__ ei, int n_edges) {
    const int e4 = (blockIdx.x * blockDim.x + threadIdx.x) * 4;
    if (e4 + 3 < n_edges) {
        const int4 r = *(const int4*)(ei + e4);
        const int4 c = *(const int4*)(ei + n_edges + e4);
        int p0 = -1, p1 = -1, p2 = -1, p3 = -1;
        if ((unsigned)r.x < NN && (unsigned)c.x < NN) p0 = atomicAdd(&g_cursor[c.x], 1);
        if ((unsigned)r.y < NN && (unsigned)c.y < NN) p1 = atomicAdd(&g_cursor[c.y], 1);
        if ((unsigned)r.z < NN && (unsigned)c.z < NN) p2 = atomicAdd(&g_cursor[c.z], 1);
        if ((unsigned)r.w < NN && (unsigned)c.w < NN) p3 = atomicAdd(&g_cursor[c.w], 1);
        if (p0 >= 0) g_csr_src[p0] = r.x;
        if (p1 >= 0) g_csr_src[p1] = r.y;
        if (p2 >= 0) g_csr_src[p2] = r.z;
        if (p3 >= 0) g_csr_src[p3] = r.w;
    } else {
        for (int e = e4; e < n_edges; e++) {
            const int row = ei[e];
            const int col = ei[n_edges + e];
            if ((unsigned)row < NN && (unsigned)col < NN) {
                int pos = atomicAdd(&g_cursor[col], 1);
                g_csr_src[pos] = row;
            }
        }
    }
}

// ---------------------------------------------------------------------------
// 2) h = x @ W via tf32 mma.sync, 3-stage cp.async pipeline.
//    g = h * dinv[row] -> g_half (fp16).
// ---------------------------------------------------------------------------
__device__ __forceinline__ unsigned f2tf32(float f) {
    unsigned r;
    asm("cvt.rna.tf32.f32 %0, %1;" : "=r"(r) : "f"(f));
    return r;
}

__device__ __forceinline__ void mma_tf32(float c[4], const unsigned a[4],
                                         const unsigned b[2]) {
    asm volatile(
        "mma.sync.aligned.m16n8k8.row.col.f32.tf32.tf32.f32 "
        "{%0,%1,%2,%3}, {%4,%5,%6,%7}, {%8,%9}, {%0,%1,%2,%3};"
        : "+f"(c[0]), "+f"(c[1]), "+f"(c[2]), "+f"(c[3])
        : "r"(a[0]), "r"(a[1]), "r"(a[2]), "r"(a[3]), "r"(b[0]), "r"(b[1]));
}

__device__ __forceinline__ void cp16(void* smem_dst, const void* gmem_src, bool pred) {
    unsigned saddr = (unsigned)__cvta_generic_to_shared(smem_dst);
    int sz = pred ? 16 : 0;
    asm volatile("cp.async.cg.shared.global [%0], [%1], 16, %2;"
                 :: "r"(saddr), "l"(gmem_src), "r"(sz));
}
#define CP_COMMIT()  asm volatile("cp.async.commit_group;")
#define CP_WAIT(N)   asm volatile("cp.async.wait_group %0;" :: "n"(N))

#define AS_STRIDE 20
#define BS_STRIDE 68

__global__ __launch_bounds__(256) void gemm_tc_kernel(
    const float* __restrict__ x, const float* __restrict__ W, int n)
{
    __shared__ unsigned As[3][128 * AS_STRIDE];  // raw f32 bits
    __shared__ unsigned Bs[3][16 * BS_STRIDE];

    const int tid  = threadIdx.x;
    const int wid  = tid >> 5;
    const int lane = tid & 31;
    const int gid  = lane >> 2;
    const int tig  = lane & 3;
    const int wm   = wid & 3;
    const int wn   = wid >> 2;
    const int m0   = blockIdx.x * 128;

    const int r0  = tid >> 2;
    const int r1  = r0 + 64;
    const int c4x = (tid & 3) * 4;
    const int rW  = tid >> 4;
    const int c4W = (tid & 15) * 4;

    auto load_stage = [&](int st, int bk) {
        const int k0 = bk * 16;
        {
            const int gr = m0 + r0;
            const bool p = gr < n;
            const float* src = x + (size_t)(p ? gr : 0) * IN_CH + k0 + c4x;
            cp16(&As[st][r0 * AS_STRIDE + c4x], src, p);
        }
        {
            const int gr = m0 + r1;
            const bool p = gr < n;
            const float* src = x + (size_t)(p ? gr : 0) * IN_CH + k0 + c4x;
            cp16(&As[st][r1 * AS_STRIDE + c4x], src, p);
        }
        cp16(&Bs[st][rW * BS_STRIDE + c4W], W + (size_t)(k0 + rW) * OUT_CH + c4W, true);
        CP_COMMIT();
    };

    float c[2][4][4];
#pragma unroll
    for (int s = 0; s < 2; s++)
#pragma unroll
        for (int t = 0; t < 4; t++)
#pragma unroll
            for (int f = 0; f < 4; f++) c[s][t][f] = 0.0f;

    load_stage(0, 0);
    load_stage(1, 1);

    for (int bk = 0; bk < NKSTEPS; bk++) {
        const int cur = bk % 3;
        if (bk + 2 < NKSTEPS) {
            load_stage((bk + 2) % 3, bk + 2);
            CP_WAIT(2);
        } else if (bk + 1 < NKSTEPS) {
            CP_WAIT(1);
        } else {
            CP_WAIT(0);
        }
        __syncthreads();

#pragma unroll
        for (int ks = 0; ks < 2; ks++) {
            const int kb = ks * 8;
            unsigned a[2][4];
#pragma unroll
            for (int s = 0; s < 2; s++) {
                const int rbase = (wm * 32 + s * 16 + gid) * AS_STRIDE;
                a[s][0] = f2tf32(__uint_as_float(As[cur][rbase + kb + tig]));
                a[s][1] = f2tf32(__uint_as_float(As[cur][rbase + 8 * AS_STRIDE + kb + tig]));
                a[s][2] = f2tf32(__uint_as_float(As[cur][rbase + kb + tig + 4]));
                a[s][3] = f2tf32(__uint_as_float(As[cur][rbase + 8 * AS_STRIDE + kb + tig + 4]));
            }
            unsigned b[4][2];
#pragma unroll
            for (int t = 0; t < 4; t++) {
                const int nb = wn * 32 + t * 8 + gid;
                b[t][0] = f2tf32(__uint_as_float(Bs[cur][(kb + tig) * BS_STRIDE + nb]));
                b[t][1] = f2tf32(__uint_as_float(Bs[cur][(kb + tig + 4) * BS_STRIDE + nb]));
            }
#pragma unroll
            for (int s = 0; s < 2; s++)
#pragma unroll
                for (int t = 0; t < 4; t++)
                    mma_tf32(c[s][t], a[s], b[t]);
        }
        __syncthreads();
    }

    // epilogue: scale by dinv[row], convert to fp16, write g_half
#pragma unroll
    for (int s = 0; s < 2; s++) {
#pragma unroll
        for (int h = 0; h < 2; h++) {
            const int row = m0 + wm * 32 + s * 16 + gid + h * 8;
            if (row < n) {
                const float di = g_dinv[row];
#pragma unroll
                for (int t = 0; t < 4; t++) {
                    const int col = wn * 32 + t * 8 + tig * 2;
                    const float vx = c[s][t][h * 2 + 0] * di;
                    const float vy = c[s][t][h * 2 + 1] * di;
                    g_half[(size_t)row * 32 + (col >> 1)] = __floats2half2_rn(vx, vy);
                }
            }
        }
    }
}

// ---------------------------------------------------------------------------
// 3) pull v3: one warp per node, QUARTER-WARP (8 lanes) per source row.
//    Each lane loads uint4 (16 B = 8 cols); 16 distinct rows in flight per
//    16-edge batch. Two-level shfl_xor combine.
// ---------------------------------------------------------------------------
__device__ __forceinline__ float2 h2f2(unsigned u) {
    return __half22float2(*(__half2*)&u);
}

__global__ __launch_bounds__(256) void pull_kernel(
    float* __restrict__ out, const float* __restrict__ bias, int n)
{
    const int warp = (blockIdx.x * 256 + threadIdx.x) >> 5;
    const int lane = threadIdx.x & 31;
    if (warp >= n) return;
    const int q  = lane >> 3;        // quarter 0..3
    const int ql = lane & 7;         // lane in quarter

    const int start = g_row_start[warp];
    const int end   = g_row_start[warp + 1];

    const uint4* rows = (const uint4*)g_half;   // 8 uint4 (128 B) per row

    float2 a0 = make_float2(0.f, 0.f), a1 = a0, a2 = a0, a3 = a0;

    // self loop g[c] — quarter 0 only (counted once after combine)
    if (q == 0) {
        uint4 r = rows[(size_t)warp * 8 + ql];
        a0 = h2f2(r.x); a1 = h2f2(r.y); a2 = h2f2(r.z); a3 = h2f2(r.w);
    }

    for (int j = start; j < end; j += 32) {
        const int id  = (j + lane < end) ? g_csr_src[j + lane] : 0;
        const int cnt = min(32, end - j);
        for (int k = 0; k < cnt; k += 16) {
            uint4 raw[4];
#pragma unroll
            for (int u = 0; u < 4; u++) {
                const int idx = k + u * 4 + q;           // this quarter's edge
                const int src = __shfl_sync(0xffffffff, id, idx & 31);
                raw[u] = (idx < cnt) ? rows[(size_t)src * 8 + ql]
                                     : make_uint4(0u, 0u, 0u, 0u);
            }
#pragma unroll
            for (int u = 0; u < 4; u++) {
                float2 t;
                t = h2f2(raw[u].x); a0.x += t.x; a0.y += t.y;
                t = h2f2(raw[u].y); a1.x += t.x; a1.y += t.y;
                t = h2f2(raw[u].z); a2.x += t.x; a2.y += t.y;
                t = h2f2(raw[u].w); a3.x += t.x; a3.y += t.y;
            }
        }
    }

    // combine quarters: xor 8 then xor 16
#pragma unroll
    for (int d = 8; d <= 16; d <<= 1) {
        a0.x += __shfl_xor_sync(0xffffffff, a0.x, d);
        a0.y += __shfl_xor_sync(0xffffffff, a0.y, d);
        a1.x += __shfl_xor_sync(0xffffffff, a1.x, d);
        a1.y += __shfl_xor_sync(0xffffffff, a1.y, d);
        a2.x += __shfl_xor_sync(0xffffffff, a2.x, d);
        a2.y += __shfl_xor_sync(0xffffffff, a2.y, d);
        a3.x += __shfl_xor_sync(0xffffffff, a3.x, d);
        a3.y += __shfl_xor_sync(0xffffffff, a3.y, d);
    }

    if (lane < 8) {                  // q == 0 writes cols [ql*8, ql*8+8)
        const float di = g_dinv[warp];
        const float4 b0 = ((const float4*)bias)[ql * 2 + 0];
        const float4 b1 = ((const float4*)bias)[ql * 2 + 1];
        float4 o0, o1;
        o0.x = a0.x * di + b0.x;  o0.y = a0.y * di + b0.y;
        o0.z = a1.x * di + b0.z;  o0.w = a1.y * di + b0.w;
        o1.x = a2.x * di + b1.x;  o1.y = a2.y * di + b1.y;
        o1.z = a3.x * di + b1.z;  o1.w = a3.y * di + b1.w;
        ((float4*)out)[(size_t)warp * 16 + ql * 2 + 0] = o0;
        ((float4*)out)[(size_t)warp * 16 + ql * 2 + 1] = o1;
    }
}

// ---------------------------------------------------------------------------
extern "C" void kernel_launch(void* const* d_in, const int* in_sizes, int n_in,
                              void* d_out, int out_size)
{
    const float* x  = (const float*)d_in[0];
    const int*   ei = (const int*)d_in[1];     // int32 edge_index [2, E]
    const float* W  = (const float*)d_in[2];
    const float* b  = (const float*)d_in[3];
    float*       out = (float*)d_out;

    const int n = in_sizes[0] / IN_CH;   // 100000
    const int e = in_sizes[1] / 2;       // 1600000

    void* p = nullptr;
    cudaGetSymbolAddress(&p, g_deg);
    cudaMemsetAsync(p, 0, (size_t)n * sizeof(int));
    cudaGetSymbolAddress(&p, g_scan_state);
    cudaMemsetAsync(p, 0, 512 * sizeof(unsigned long long));

    const int e4blocks = (e / 4 + 255) / 256;
    count_deg_kernel<<<e4blocks, 256>>>(ei, e);

    const int nb = (n + 255) / 256;
    scan_kernel<<<nb, 256>>>(n);     // warp-parallel lookback scan + dinv

    gemm_tc_kernel<<<(n + 127) / 128, 256>>>(x, W, n);

    fill_csr_kernel<<<e4blocks, 256>>>(ei, e);

    pull_kernel<<<(n * 32 + 255) / 256, 256>>>(out, b, n);
}

// round 14
// speedup vs baseline: 1.1303x; 1.0572x over previous
#include <cuda_runtime.h>
#include <cuda_fp16.h>
#include <cstdint>

#define NN 100000
#define NE 1600000
#define IN_CH 128
#define OUT_CH 64
#define NKSTEPS (IN_CH / 16)   // 8

// Scratch (device globals: no allocation allowed in kernel_launch).
__device__ int     g_deg[NN];
__device__ float   g_dinv[NN];
__device__ __half2 g_half[(size_t)NN * 32];   // g = (x@W)*dinv[row], fp16, 12.8 MB
__device__ unsigned long long g_scan_state[512];   // decoupled-lookback flags
__device__ int     g_row_start[NN + 1];
__device__ int     g_rank[NE];                // edge's rank within its col bucket
__device__ int     g_csr_src[NE];

// ---------------------------------------------------------------------------
// 1) degree counting; the atomicAdd return IS the edge's bucket rank -> store.
//    (g_deg / g_scan_state zeroed by cudaMemsetAsync host-side.)
// ---------------------------------------------------------------------------
__global__ void count_deg_kernel(const int* __restrict__ ei, int n_edges) {
    const int e4 = (blockIdx.x * blockDim.x + threadIdx.x) * 4;
    if (e4 + 3 < n_edges) {
        const int4 r = *(const int4*)(ei + e4);
        const int4 c = *(const int4*)(ei + n_edges + e4);
        int4 rk = make_int4(-1, -1, -1, -1);
        if ((unsigned)r.x < NN && (unsigned)c.x < NN) rk.x = atomicAdd(&g_deg[c.x], 1);
        if ((unsigned)r.y < NN && (unsigned)c.y < NN) rk.y = atomicAdd(&g_deg[c.y], 1);
        if ((unsigned)r.z < NN && (unsigned)c.z < NN) rk.z = atomicAdd(&g_deg[c.z], 1);
        if ((unsigned)r.w < NN && (unsigned)c.w < NN) rk.w = atomicAdd(&g_deg[c.w], 1);
        *(int4*)(g_rank + e4) = rk;            // coalesced
    } else {
        for (int e = e4; e < n_edges; e++) {
            const int row = ei[e];
            const int col = ei[n_edges + e];
            int rk = -1;
            if ((unsigned)row < NN && (unsigned)col < NN)
                rk = atomicAdd(&g_deg[col], 1);
            g_rank[e] = rk;
        }
    }
}

// ---------------------------------------------------------------------------
// 1b) single-pass exclusive scan, warp-parallel decoupled lookback.
//     Writes row_start and fused dinv.
// ---------------------------------------------------------------------------
__global__ void scan_kernel(int n) {
    __shared__ int s[256];
    __shared__ int s_prefix;
    const int bid = blockIdx.x;
    const int i   = bid * 256 + threadIdx.x;
    const int v   = (i < n) ? g_deg[i] : 0;

    s[threadIdx.x] = v;
    __syncthreads();
    for (int off = 1; off < 256; off <<= 1) {
        int u = (threadIdx.x >= off) ? s[threadIdx.x - off] : 0;
        __syncthreads();
        s[threadIdx.x] += u;
        __syncthreads();
    }
    const int incl = s[threadIdx.x];
    const int agg  = s[255];

    if (threadIdx.x < 32) {
        const int lane = threadIdx.x;
        if (bid == 0) {
            if (lane == 0) {
                atomicExch(&g_scan_state[0], (2ULL << 62) | (unsigned)agg);
                s_prefix = 0;
            }
        } else {
            if (lane == 0)
                atomicExch(&g_scan_state[bid], (1ULL << 62) | (unsigned)agg);
            __syncwarp();

            int pre  = 0;
            int wend = bid;
            while (true) {
                const int idx = wend - 32 + lane;
                unsigned long long st = (idx >= 0)
                    ? atomicAdd(&g_scan_state[idx], 0ULL)
                    : (2ULL << 62);
                while ((st >> 62) == 0ULL) {
                    __nanosleep(20);
                    st = atomicAdd(&g_scan_state[idx], 0ULL);
                }
                const unsigned done = __ballot_sync(0xffffffff, (st >> 62) == 2ULL);
                int val = (idx >= 0) ? (int)(st & 0xffffffffULL) : 0;
                if (done) {
                    const int highest = 31 - __clz(done);
                    if (lane < highest) val = 0;
#pragma unroll
                    for (int d = 16; d; d >>= 1) val += __shfl_down_sync(0xffffffff, val, d);
                    pre += __shfl_sync(0xffffffff, val, 0);
                    break;
                } else {
#pragma unroll
                    for (int d = 16; d; d >>= 1) val += __shfl_down_sync(0xffffffff, val, d);
                    pre += __shfl_sync(0xffffffff, val, 0);
                    wend -= 32;
                }
            }
            if (lane == 0) {
                atomicExch(&g_scan_state[bid], (2ULL << 62) | (unsigned)(pre + agg));
                s_prefix = pre;
            }
        }
    }
    __syncthreads();

    const int excl = s_prefix + incl - v;
    if (i < n) {
        g_row_start[i] = excl;
        g_dinv[i]      = rsqrtf((float)(v + 1));   // +1 self loop (fused)
        if (i == n - 1) g_row_start[n] = excl + v;
    }
}

// ---------------------------------------------------------------------------
// 1c) fill CSR, ATOMIC-FREE: slot = row_start[col] + rank[e].
//     x4 unroll -> 4 independent random L2 loads in flight.
// ---------------------------------------------------------------------------
__global__ void fill_csr_kernel(const int* __restrict__ ei, int n_edges) {
    const int e4 = (blockIdx.x * blockDim.x + threadIdx.x) * 4;
    if (e4 + 3 < n_edges) {
        const int4 r  = *(const int4*)(ei + e4);
        const int4 c  = *(const int4*)(ei + n_edges + e4);
        const int4 rk = *(const int4*)(g_rank + e4);
        int s0 = (rk.x >= 0) ? g_row_start[c.x] : 0;
        int s1 = (rk.y >= 0) ? g_row_start[c.y] : 0;
        int s2 = (rk.z >= 0) ? g_row_start[c.z] : 0;
        int s3 = (rk.w >= 0) ? g_row_start[c.w] : 0;
        if (rk.x >= 0) g_csr_src[s0 + rk.x] = r.x;
        if (rk.y >= 0) g_csr_src[s1 + rk.y] = r.y;
        if (rk.z >= 0) g_csr_src[s2 + rk.z] = r.z;
        if (rk.w >= 0) g_csr_src[s3 + rk.w] = r.w;
    } else {
        for (int e = e4; e < n_edges; e++) {
            const int row = ei[e];
            const int col = ei[n_edges + e];
            const int rk  = g_rank[e];
            if (rk >= 0) g_csr_src[g_row_start[col] + rk] = row;
        }
    }
}

// ---------------------------------------------------------------------------
// 2) h = x @ W via tf32 mma.sync, 3-stage cp.async pipeline.
//    g = h * dinv[row] -> g_half (fp16).
// ---------------------------------------------------------------------------
__device__ __forceinline__ unsigned f2tf32(float f) {
    unsigned r;
    asm("cvt.rna.tf32.f32 %0, %1;" : "=r"(r) : "f"(f));
    return r;
}

__device__ __forceinline__ void mma_tf32(float c[4], const unsigned a[4],
                                         const unsigned b[2]) {
    asm volatile(
        "mma.sync.aligned.m16n8k8.row.col.f32.tf32.tf32.f32 "
        "{%0,%1,%2,%3}, {%4,%5,%6,%7}, {%8,%9}, {%0,%1,%2,%3};"
        : "+f"(c[0]), "+f"(c[1]), "+f"(c[2]), "+f"(c[3])
        : "r"(a[0]), "r"(a[1]), "r"(a[2]), "r"(a[3]), "r"(b[0]), "r"(b[1]));
}

__device__ __forceinline__ void cp16(void* smem_dst, const void* gmem_src, bool pred) {
    unsigned saddr = (unsigned)__cvta_generic_to_shared(smem_dst);
    int sz = pred ? 16 : 0;
    asm volatile("cp.async.cg.shared.global [%0], [%1], 16, %2;"
                 :: "r"(saddr), "l"(gmem_src), "r"(sz));
}
#define CP_COMMIT()  asm volatile("cp.async.commit_group;")
#define CP_WAIT(N)   asm volatile("cp.async.wait_group %0;" :: "n"(N))

#define AS_STRIDE 20
#define BS_STRIDE 68

__global__ __launch_bounds__(256) void gemm_tc_kernel(
    const float* __restrict__ x, const float* __restrict__ W, int n)
{
    __shared__ unsigned As[3][128 * AS_STRIDE];
    __shared__ unsigned Bs[3][16 * BS_STRIDE];

    const int tid  = threadIdx.x;
    const int wid  = tid >> 5;
    const int lane = tid & 31;
    const int gid  = lane >> 2;
    const int tig  = lane & 3;
    const int wm   = wid & 3;
    const int wn   = wid >> 2;
    const int m0   = blockIdx.x * 128;

    const int r0  = tid >> 2;
    const int r1  = r0 + 64;
    const int c4x = (tid & 3) * 4;
    const int rW  = tid >> 4;
    const int c4W = (tid & 15) * 4;

    auto load_stage = [&](int st, int bk) {
        const int k0 = bk * 16;
        {
            const int gr = m0 + r0;
            const bool p = gr < n;
            const float* src = x + (size_t)(p ? gr : 0) * IN_CH + k0 + c4x;
            cp16(&As[st][r0 * AS_STRIDE + c4x], src, p);
        }
        {
            const int gr = m0 + r1;
            const bool p = gr < n;
            const float* src = x + (size_t)(p ? gr : 0) * IN_CH + k0 + c4x;
            cp16(&As[st][r1 * AS_STRIDE + c4x], src, p);
        }
        cp16(&Bs[st][rW * BS_STRIDE + c4W], W + (size_t)(k0 + rW) * OUT_CH + c4W, true);
        CP_COMMIT();
    };

    float c[2][4][4];
#pragma unroll
    for (int s = 0; s < 2; s++)
#pragma unroll
        for (int t = 0; t < 4; t++)
#pragma unroll
            for (int f = 0; f < 4; f++) c[s][t][f] = 0.0f;

    load_stage(0, 0);
    load_stage(1, 1);

    for (int bk = 0; bk < NKSTEPS; bk++) {
        const int cur = bk % 3;
        if (bk + 2 < NKSTEPS) {
            load_stage((bk + 2) % 3, bk + 2);
            CP_WAIT(2);
        } else if (bk + 1 < NKSTEPS) {
            CP_WAIT(1);
        } else {
            CP_WAIT(0);
        }
        __syncthreads();

#pragma unroll
        for (int ks = 0; ks < 2; ks++) {
            const int kb = ks * 8;
            unsigned a[2][4];
#pragma unroll
            for (int s = 0; s < 2; s++) {
                const int rbase = (wm * 32 + s * 16 + gid) * AS_STRIDE;
                a[s][0] = f2tf32(__uint_as_float(As[cur][rbase + kb + tig]));
                a[s][1] = f2tf32(__uint_as_float(As[cur][rbase + 8 * AS_STRIDE + kb + tig]));
                a[s][2] = f2tf32(__uint_as_float(As[cur][rbase + kb + tig + 4]));
                a[s][3] = f2tf32(__uint_as_float(As[cur][rbase + 8 * AS_STRIDE + kb + tig + 4]));
            }
            unsigned b[4][2];
#pragma unroll
            for (int t = 0; t < 4; t++) {
                const int nb = wn * 32 + t * 8 + gid;
                b[t][0] = f2tf32(__uint_as_float(Bs[cur][(kb + tig) * BS_STRIDE + nb]));
                b[t][1] = f2tf32(__uint_as_float(Bs[cur][(kb + tig + 4) * BS_STRIDE + nb]));
            }
#pragma unroll
            for (int s = 0; s < 2; s++)
#pragma unroll
                for (int t = 0; t < 4; t++)
                    mma_tf32(c[s][t], a[s], b[t]);
        }
        __syncthreads();
    }

#pragma unroll
    for (int s = 0; s < 2; s++) {
#pragma unroll
        for (int h = 0; h < 2; h++) {
            const int row = m0 + wm * 32 + s * 16 + gid + h * 8;
            if (row < n) {
                const float di = g_dinv[row];
#pragma unroll
                for (int t = 0; t < 4; t++) {
                    const int col = wn * 32 + t * 8 + tig * 2;
                    const float vx = c[s][t][h * 2 + 0] * di;
                    const float vy = c[s][t][h * 2 + 1] * di;
                    g_half[(size_t)row * 32 + (col >> 1)] = __floats2half2_rn(vx, vy);
                }
            }
        }
    }
}

// ---------------------------------------------------------------------------
// 3) pull v3: one warp per node, quarter-warp (8 lanes) per source row.
// ---------------------------------------------------------------------------
__device__ __forceinline__ float2 h2f2(unsigned u) {
    return __half22float2(*(__half2*)&u);
}

__global__ __launch_bounds__(256) void pull_kernel(
    float* __restrict__ out, const float* __restrict__ bias, int n)
{
    const int warp = (blockIdx.x * 256 + threadIdx.x) >> 5;
    const int lane = threadIdx.x & 31;
    if (warp >= n) return;
    const int q  = lane >> 3;
    const int ql = lane & 7;

    const int start = g_row_start[warp];
    const int end   = g_row_start[warp + 1];

    const uint4* rows = (const uint4*)g_half;

    float2 a0 = make_float2(0.f, 0.f), a1 = a0, a2 = a0, a3 = a0;

    if (q == 0) {   // self loop, counted once
        uint4 r = rows[(size_t)warp * 8 + ql];
        a0 = h2f2(r.x); a1 = h2f2(r.y); a2 = h2f2(r.z); a3 = h2f2(r.w);
    }

    for (int j = start; j < end; j += 32) {
        const int id  = (j + lane < end) ? g_csr_src[j + lane] : 0;
        const int cnt = min(32, end - j);
        for (int k = 0; k < cnt; k += 16) {
            uint4 raw[4];
#pragma unroll
            for (int u = 0; u < 4; u++) {
                const int idx = k + u * 4 + q;
                const int src = __shfl_sync(0xffffffff, id, idx & 31);
                raw[u] = (idx < cnt) ? rows[(size_t)src * 8 + ql]
                                     : make_uint4(0u, 0u, 0u, 0u);
            }
#pragma unroll
            for (int u = 0; u < 4; u++) {
                float2 t;
                t = h2f2(raw[u].x); a0.x += t.x; a0.y += t.y;
                t = h2f2(raw[u].y); a1.x += t.x; a1.y += t.y;
                t = h2f2(raw[u].z); a2.x += t.x; a2.y += t.y;
                t = h2f2(raw[u].w); a3.x += t.x; a3.y += t.y;
            }
        }
    }

#pragma unroll
    for (int d = 8; d <= 16; d <<= 1) {
        a0.x += __shfl_xor_sync(0xffffffff, a0.x, d);
        a0.y += __shfl_xor_sync(0xffffffff, a0.y, d);
        a1.x += __shfl_xor_sync(0xffffffff, a1.x, d);
        a1.y += __shfl_xor_sync(0xffffffff, a1.y, d);
        a2.x += __shfl_xor_sync(0xffffffff, a2.x, d);
        a2.y += __shfl_xor_sync(0xffffffff, a2.y, d);
        a3.x += __shfl_xor_sync(0xffffffff, a3.x, d);
        a3.y += __shfl_xor_sync(0xffffffff, a3.y, d);
    }

    if (lane < 8) {
        const float di = g_dinv[warp];
        const float4 b0 = ((const float4*)bias)[ql * 2 + 0];
        const float4 b1 = ((const float4*)bias)[ql * 2 + 1];
        float4 o0, o1;
        o0.x = a0.x * di + b0.x;  o0.y = a0.y * di + b0.y;
        o0.z = a1.x * di + b0.z;  o0.w = a1.y * di + b0.w;
        o1.x = a2.x * di + b1.x;  o1.y = a2.y * di + b1.y;
        o1.z = a3.x * di + b1.z;  o1.w = a3.y * di + b1.w;
        ((float4*)out)[(size_t)warp * 16 + ql * 2 + 0] = o0;
        ((float4*)out)[(size_t)warp * 16 + ql * 2 + 1] = o1;
    }
}

// ---------------------------------------------------------------------------
extern "C" void kernel_launch(void* const* d_in, const int* in_sizes, int n_in,
                              void* d_out, int out_size)
{
    const float* x  = (const float*)d_in[0];
    const int*   ei = (const int*)d_in[1];     // int32 edge_index [2, E]
    const float* W  = (const float*)d_in[2];
    const float* b  = (const float*)d_in[3];
    float*       out = (float*)d_out;

    const int n = in_sizes[0] / IN_CH;   // 100000
    const int e = in_sizes[1] / 2;       // 1600000

    // side stream + events for the GEMM || fill fork (created once; handles
    // are cached — deterministic identical work every call)
    static cudaStream_t s2 = nullptr;
    static cudaEvent_t  ev_fork = nullptr, ev_join = nullptr;
    if (s2 == nullptr) {
        cudaStreamCreateWithFlags(&s2, cudaStreamNonBlocking);
        cudaEventCreateWithFlags(&ev_fork, cudaEventDisableTiming);
        cudaEventCreateWithFlags(&ev_join, cudaEventDisableTiming);
    }

    void* p = nullptr;
    cudaGetSymbolAddress(&p, g_deg);
    cudaMemsetAsync(p, 0, (size_t)n * sizeof(int));
    cudaGetSymbolAddress(&p, g_scan_state);
    cudaMemsetAsync(p, 0, 512 * sizeof(unsigned long long));

    const int e4blocks = (e / 4 + 255) / 256;
    count_deg_kernel<<<e4blocks, 256>>>(ei, e);

    const int nb = (n + 255) / 256;
    scan_kernel<<<nb, 256>>>(n);

    // fork: fill on s2, GEMM on main stream — independent after scan
    cudaEventRecord(ev_fork, 0);
    cudaStreamWaitEvent(s2, ev_fork, 0);
    fill_csr_kernel<<<e4blocks, 256, 0, s2>>>(ei, e);
    cudaEventRecord(ev_join, s2);

    gemm_tc_kernel<<<(n + 127) / 128, 256>>>(x, W, n);

    // join: pull needs both g_half (main) and g_csr_src (s2)
    cudaStreamWaitEvent(0, ev_join, 0);
    pull_kernel<<<(n * 32 + 255) / 256, 256>>>(out, b, n);
}